// round 16
// baseline (speedup 1.0000x reference)
#include <cuda_runtime.h>
#include <math.h>
#include <stdint.h>

// ---------------- problem constants ----------------
#define B_   4
#define L_   512
#define D_   512
#define NH_  8
#define FF_  2048
#define NL_  4
#define DS_  64
#define DC_  4
#define DI_  1024
#define DTR_ 32
#define HD_  64
#define R_   (B_ * L_)            // 2048 token rows
#define XD_  (DTR_ + 2 * DS_)     // 160

// ---------------- device scratch (no allocs allowed) ----------------
__device__ float g_x    [R_ * D_];          // running activation
__device__ float g_qkv  [R_ * 3 * D_];
__device__ float g_scores[B_ * NH_ * L_ * L_];
__device__ float g_ctx  [R_ * D_];
__device__ float g_a    [R_ * D_];          // attn out, then attn+mamba
__device__ float g_xz   [R_ * 2 * DI_];
__device__ float g_xc   [R_ * DI_];
__device__ float g_xdbl [R_ * XD_];
__device__ float g_dt   [R_ * DI_];
__device__ float g_y    [R_ * DI_];
__device__ float g_ff   [R_ * FF_];
__device__ float g_h2   [R_ * D_];

// ---------------- positional encoding ----------------
__global__ __launch_bounds__(256) void pos_encode_kernel(const float* __restrict__ src) {
    int idx = blockIdx.x * blockDim.x + threadIdx.x;
    if (idx >= R_ * D_) return;
    int d = idx % D_;
    int l = (idx / D_) % L_;
    int i2 = d & ~1;  // 2*(d/2)
    float div = expf(-(float)i2 * (9.210340371976184f / (float)D_));  // ln(10000)/D
    float ang = (float)l * div;
    float pe = (d & 1) ? cosf(ang) : sinf(ang);
    g_x[idx] = src[idx] + pe;
}

// ---------------- generic SGEMM: C = act(A(M,K) @ W(N,K)^T + bias [+ C]) ----------------
__global__ __launch_bounds__(256) void gemm_nt_kernel(
    const float* __restrict__ A, int lda,
    const float* __restrict__ W, int ldb,
    const float* __restrict__ bias,
    float* __restrict__ C, int ldc,
    int M, int N, int K, int act, int accum)
{
    __shared__ float As[16][68];
    __shared__ float Ws[16][68];
    const int tid = threadIdx.x;
    const int m0 = blockIdx.y * 64, n0 = blockIdx.x * 64;
    const int tr = tid >> 4, tc = tid & 15;

    float acc[4][4];
#pragma unroll
    for (int i = 0; i < 4; ++i)
#pragma unroll
        for (int j = 0; j < 4; ++j) acc[i][j] = 0.f;

    for (int k0 = 0; k0 < K; k0 += 16) {
#pragma unroll
        for (int i = 0; i < 4; ++i) {
            int idx = tid + i * 256;
            int r = idx >> 4, c = idx & 15;
            int m = m0 + r, k = k0 + c;
            float v = 0.f;
            if (m < M && k < K) v = A[(size_t)m * lda + k];
            As[c][r] = v;
        }
#pragma unroll
        for (int i = 0; i < 4; ++i) {
            int idx = tid + i * 256;
            int r = idx >> 4, c = idx & 15;
            int n = n0 + r, k = k0 + c;
            float v = 0.f;
            if (n < N && k < K) v = W[(size_t)n * ldb + k];
            Ws[c][r] = v;
        }
        __syncthreads();
#pragma unroll
        for (int kk = 0; kk < 16; ++kk) {
            float4 a4 = *reinterpret_cast<const float4*>(&As[kk][tr * 4]);
            float4 b4 = *reinterpret_cast<const float4*>(&Ws[kk][tc * 4]);
            float a[4] = {a4.x, a4.y, a4.z, a4.w};
            float b[4] = {b4.x, b4.y, b4.z, b4.w};
#pragma unroll
            for (int i = 0; i < 4; ++i)
#pragma unroll
                for (int j = 0; j < 4; ++j)
                    acc[i][j] = fmaf(a[i], b[j], acc[i][j]);
        }
        __syncthreads();
    }

#pragma unroll
    for (int i = 0; i < 4; ++i) {
        int m = m0 + tr * 4 + i;
        if (m >= M) continue;
#pragma unroll
        for (int j = 0; j < 4; ++j) {
            int n = n0 + tc * 4 + j;
            if (n >= N) continue;
            float v = acc[i][j];
            if (bias) v += bias[n];
            if (accum) v += C[(size_t)m * ldc + n];
            if (act == 1) v = fmaxf(v, 0.f);
            else if (act == 2) v = (v > 20.f) ? v : log1pf(expf(v));   // softplus
            C[(size_t)m * ldc + n] = v;
        }
    }
}

// ---------------- attention: scores = Q K^T / sqrt(HD) ----------------
// grid (8, 8, B*NH), 256 threads. qkv row layout: [q(512) | k(512) | v(512)]
__global__ __launch_bounds__(256) void attn_scores_kernel() {
    __shared__ float Qs[64][68];
    __shared__ float Ks[64][68];
    const int tid = threadIdx.x;
    const int z = blockIdx.z;
    const int b = z >> 3, h = z & 7;
    const int m0 = blockIdx.y * 64, n0 = blockIdx.x * 64;
    const float* Qb = g_qkv + (size_t)b * L_ * 1536 + h * 64;
    const float* Kb = Qb + 512;

#pragma unroll
    for (int i = 0; i < 16; ++i) {
        int idx = tid + i * 256;
        int r = idx >> 6, c = idx & 63;
        Qs[c][r] = Qb[(size_t)(m0 + r) * 1536 + c];
        Ks[c][r] = Kb[(size_t)(n0 + r) * 1536 + c];
    }
    __syncthreads();

    const int tr = tid >> 4, tc = tid & 15;
    float acc[4][4];
#pragma unroll
    for (int i = 0; i < 4; ++i)
#pragma unroll
        for (int j = 0; j < 4; ++j) acc[i][j] = 0.f;

#pragma unroll 8
    for (int kk = 0; kk < 64; ++kk) {
        float4 a4 = *reinterpret_cast<const float4*>(&Qs[kk][tr * 4]);
        float4 b4 = *reinterpret_cast<const float4*>(&Ks[kk][tc * 4]);
        float a[4] = {a4.x, a4.y, a4.z, a4.w};
        float b[4] = {b4.x, b4.y, b4.z, b4.w};
#pragma unroll
        for (int i = 0; i < 4; ++i)
#pragma unroll
            for (int j = 0; j < 4; ++j)
                acc[i][j] = fmaf(a[i], b[j], acc[i][j]);
    }

    float* Sb = g_scores + (size_t)z * L_ * L_;
#pragma unroll
    for (int i = 0; i < 4; ++i) {
        int m = m0 + tr * 4 + i;
#pragma unroll
        for (int j = 0; j < 4; ++j) {
            int n = n0 + tc * 4 + j;
            Sb[(size_t)m * L_ + n] = acc[i][j] * 0.125f;   // 1/sqrt(64)
        }
    }
}

// ---------------- row softmax over 512 cols ----------------
__global__ __launch_bounds__(256) void softmax_rows_kernel() {
    float* p = g_scores + (size_t)blockIdx.x * 512;
    const int tid = threadIdx.x;
    const int wid = tid >> 5, lane = tid & 31;
    __shared__ float rmax[8], rsum[8], bc[2];

    float s0 = p[tid], s1 = p[tid + 256];
    float m = fmaxf(s0, s1);
#pragma unroll
    for (int o = 16; o; o >>= 1) m = fmaxf(m, __shfl_xor_sync(0xffffffffu, m, o));
    if (lane == 0) rmax[wid] = m;
    __syncthreads();
    if (tid == 0) {
        float mm = rmax[0];
#pragma unroll
        for (int i = 1; i < 8; ++i) mm = fmaxf(mm, rmax[i]);
        bc[0] = mm;
    }
    __syncthreads();
    float M = bc[0];
    float e0 = __expf(s0 - M), e1 = __expf(s1 - M);
    float s = e0 + e1;
#pragma unroll
    for (int o = 16; o; o >>= 1) s += __shfl_xor_sync(0xffffffffu, s, o);
    if (lane == 0) rsum[wid] = s;
    __syncthreads();
    if (tid == 0) {
        float ss = 0.f;
#pragma unroll
        for (int i = 0; i < 8; ++i) ss += rsum[i];
        bc[1] = 1.f / ss;
    }
    __syncthreads();
    float inv = bc[1];
    p[tid] = e0 * inv;
    p[tid + 256] = e1 * inv;
}

// ---------------- attention: O = P @ V, heads merged into g_ctx ----------------
// grid (8 m-tiles, B*NH), 256 threads
__global__ __launch_bounds__(256) void attn_pv_kernel() {
    __shared__ float As[16][68];
    __shared__ float Bs[16][68];
    const int tid = threadIdx.x;
    const int z = blockIdx.y;
    const int b = z >> 3, h = z & 7;
    const int m0 = blockIdx.x * 64;
    const float* P = g_scores + (size_t)z * L_ * L_;
    const float* V = g_qkv + (size_t)b * L_ * 1536 + 1024 + h * 64;

    const int tr = tid >> 4, tc = tid & 15;
    float acc[4][4];
#pragma unroll
    for (int i = 0; i < 4; ++i)
#pragma unroll
        for (int j = 0; j < 4; ++j) acc[i][j] = 0.f;

    for (int k0 = 0; k0 < L_; k0 += 16) {
#pragma unroll
        for (int i = 0; i < 4; ++i) {
            int idx = tid + i * 256;
            int r = idx >> 4, c = idx & 15;
            As[c][r] = P[(size_t)(m0 + r) * 512 + k0 + c];
        }
#pragma unroll
        for (int i = 0; i < 4; ++i) {
            int idx = tid + i * 256;
            int kk = idx >> 6, n = idx & 63;
            Bs[kk][n] = V[(size_t)(k0 + kk) * 1536 + n];
        }
        __syncthreads();
#pragma unroll
        for (int kk = 0; kk < 16; ++kk) {
            float4 a4 = *reinterpret_cast<const float4*>(&As[kk][tr * 4]);
            float4 b4 = *reinterpret_cast<const float4*>(&Bs[kk][tc * 4]);
            float a[4] = {a4.x, a4.y, a4.z, a4.w};
            float b[4] = {b4.x, b4.y, b4.z, b4.w};
#pragma unroll
            for (int i = 0; i < 4; ++i)
#pragma unroll
                for (int j = 0; j < 4; ++j)
                    acc[i][j] = fmaf(a[i], b[j], acc[i][j]);
        }
        __syncthreads();
    }

#pragma unroll
    for (int i = 0; i < 4; ++i) {
        int m = m0 + tr * 4 + i;
#pragma unroll
        for (int j = 0; j < 4; ++j) {
            int n = tc * 4 + j;
            g_ctx[(size_t)(b * L_ + m) * D_ + h * 64 + n] = acc[i][j];
        }
    }
}

// ---------------- depthwise causal conv1d (DC=4) + SiLU ----------------
__global__ __launch_bounds__(256) void conv_silu_kernel(
    const float* __restrict__ conv_w, const float* __restrict__ conv_b)
{
    int idx = blockIdx.x * blockDim.x + threadIdx.x;
    if (idx >= R_ * DI_) return;
    int d = idx % DI_;
    int t = (idx / DI_) % L_;
    int b = idx / (DI_ * L_);
    const float* w = conv_w + d * 4;
    const float* xin = g_xz + (size_t)b * L_ * (2 * DI_) + d;
    float acc = conv_b[d];
#pragma unroll
    for (int k = 0; k < 4; ++k) {
        int tt = t - 3 + k;
        if (tt >= 0) acc = fmaf(w[k], xin[(size_t)tt * (2 * DI_)], acc);
    }
    float sig = 1.f / (1.f + __expf(-acc));
    g_xc[idx] = acc * sig;
}

// ---------------- mamba selective scan: one warp per (b,d), 2 states/lane ----------------
__global__ __launch_bounds__(256) void scan_kernel(
    const float* __restrict__ A_log, const float* __restrict__ D_skip)
{
    int w = (blockIdx.x * blockDim.x + threadIdx.x) >> 5;
    int lane = threadIdx.x & 31;
    int b = w >> 10;          // / DI_
    int d = w & (DI_ - 1);
    int n0 = lane * 2;

    float a0 = -expf(A_log[d * DS_ + n0]);
    float a1 = -expf(A_log[d * DS_ + n0 + 1]);
    float dsk = D_skip[d];
    float h0 = 0.f, h1 = 0.f;

    const float* dtp = g_dt   + (size_t)b * L_ * DI_ + d;
    const float* up  = g_xc   + (size_t)b * L_ * DI_ + d;
    const float* xd  = g_xdbl + (size_t)b * L_ * XD_;
    const float* zp  = g_xz   + (size_t)b * L_ * (2 * DI_) + DI_ + d;
    float*       yp  = g_y    + (size_t)b * L_ * DI_ + d;

    for (int t = 0; t < L_; ++t) {
        float dt = dtp[(size_t)t * DI_];
        float u  = up [(size_t)t * DI_];
        const float* row = xd + (size_t)t * XD_;
        float2 Bn = *reinterpret_cast<const float2*>(row + DTR_ + n0);
        float2 Cn = *reinterpret_cast<const float2*>(row + DTR_ + DS_ + n0);
        float e0 = __expf(dt * a0), e1 = __expf(dt * a1);
        float du = dt * u;
        h0 = fmaf(e0, h0, du * Bn.x);
        h1 = fmaf(e1, h1, du * Bn.y);
        float y = fmaf(h0, Cn.x, h1 * Cn.y);
#pragma unroll
        for (int o = 16; o; o >>= 1) y += __shfl_xor_sync(0xffffffffu, y, o);
        if (lane == 0) {
            float z = zp[(size_t)t * (2 * DI_)];
            float sil = z / (1.f + __expf(-z));
            yp[(size_t)t * DI_] = (y + u * dsk) * sil;
        }
    }
}

// ---------------- layernorm over D=512 ----------------
__global__ __launch_bounds__(256) void layernorm_kernel(
    const float* __restrict__ in, const float* __restrict__ g,
    const float* __restrict__ bta, float* __restrict__ out)
{
    const float* p = in + (size_t)blockIdx.x * D_;
    float* q = out + (size_t)blockIdx.x * D_;
    const int tid = threadIdx.x;
    const int wid = tid >> 5, lane = tid & 31;
    __shared__ float rs[8], rq[8], bc[2];

    float x0 = p[tid], x1 = p[tid + 256];
    float s = x0 + x1, sq = x0 * x0 + x1 * x1;
#pragma unroll
    for (int o = 16; o; o >>= 1) {
        s  += __shfl_xor_sync(0xffffffffu, s, o);
        sq += __shfl_xor_sync(0xffffffffu, sq, o);
    }
    if (lane == 0) { rs[wid] = s; rq[wid] = sq; }
    __syncthreads();
    if (tid == 0) {
        float S = 0.f, SQ = 0.f;
#pragma unroll
        for (int i = 0; i < 8; ++i) { S += rs[i]; SQ += rq[i]; }
        float mean = S * (1.f / D_);
        float var  = SQ * (1.f / D_) - mean * mean;
        bc[0] = mean;
        bc[1] = rsqrtf(var + 1e-5f);
    }
    __syncthreads();
    float mean = bc[0], inv = bc[1];
    q[tid]        = (x0 - mean) * inv * g[tid]        + bta[tid];
    q[tid + 256]  = (x1 - mean) * inv * g[tid + 256]  + bta[tid + 256];
}

// ---------------- host side ----------------
static void gemm(const float* A, int lda, const float* W, int ldb, const float* bias,
                 float* C, int ldc, int M, int N, int K, int act, int accum)
{
    dim3 grid((N + 63) / 64, (M + 63) / 64);
    gemm_nt_kernel<<<grid, 256>>>(A, lda, W, ldb, bias, C, ldc, M, N, K, act, accum);
}

extern "C" void kernel_launch(void* const* d_in, const int* in_sizes, int n_in,
                              void* d_out, int out_size)
{
    (void)in_sizes; (void)n_in; (void)out_size;
    const float* src    = (const float*)d_in[0];
    const float* w_qkv  = (const float*)d_in[1];
    const float* b_qkv  = (const float*)d_in[2];
    const float* w_o    = (const float*)d_in[3];
    const float* b_o    = (const float*)d_in[4];
    const float* w1     = (const float*)d_in[5];
    const float* b1     = (const float*)d_in[6];
    const float* w2     = (const float*)d_in[7];
    const float* b2     = (const float*)d_in[8];
    const float* n1g    = (const float*)d_in[9];
    const float* n1b    = (const float*)d_in[10];
    const float* inw    = (const float*)d_in[11];
    const float* cw     = (const float*)d_in[12];
    const float* cb     = (const float*)d_in[13];
    const float* xpw    = (const float*)d_in[14];
    const float* dtw    = (const float*)d_in[15];
    const float* dtb    = (const float*)d_in[16];
    const float* alog   = (const float*)d_in[17];
    const float* dskip  = (const float*)d_in[18];
    const float* outw   = (const float*)d_in[19];
    const float* nfg    = (const float*)d_in[20];
    const float* nfb    = (const float*)d_in[21];
    float* out = (float*)d_out;

    float *px, *pqkv, *pctx, *pa, *pxz, *pxc, *pxdbl, *pdt, *py, *pff, *ph2;
    cudaGetSymbolAddress((void**)&px,    g_x);
    cudaGetSymbolAddress((void**)&pqkv,  g_qkv);
    cudaGetSymbolAddress((void**)&pctx,  g_ctx);
    cudaGetSymbolAddress((void**)&pa,    g_a);
    cudaGetSymbolAddress((void**)&pxz,   g_xz);
    cudaGetSymbolAddress((void**)&pxc,   g_xc);
    cudaGetSymbolAddress((void**)&pxdbl, g_xdbl);
    cudaGetSymbolAddress((void**)&pdt,   g_dt);
    cudaGetSymbolAddress((void**)&py,    g_y);
    cudaGetSymbolAddress((void**)&pff,   g_ff);
    cudaGetSymbolAddress((void**)&ph2,   g_h2);

    pos_encode_kernel<<<(R_ * D_ + 255) / 256, 256>>>(src);

    for (int i = 0; i < NL_; ++i) {
        const float* w_qkv_i = w_qkv + (size_t)i * 3 * D_ * D_;
        const float* b_qkv_i = b_qkv + (size_t)i * 3 * D_;
        const float* w_o_i   = w_o   + (size_t)i * D_ * D_;
        const float* b_o_i   = b_o   + (size_t)i * D_;
        const float* w1_i    = w1    + (size_t)i * FF_ * D_;
        const float* b1_i    = b1    + (size_t)i * FF_;
        const float* w2_i    = w2    + (size_t)i * D_ * FF_;
        const float* b2_i    = b2    + (size_t)i * D_;
        const float* n1g_i   = n1g   + (size_t)i * D_;
        const float* n1b_i   = n1b   + (size_t)i * D_;
        const float* inw_i   = inw   + (size_t)i * 2 * DI_ * D_;
        const float* cw_i    = cw    + (size_t)i * DI_ * DC_;
        const float* cb_i    = cb    + (size_t)i * DI_;
        const float* xpw_i   = xpw   + (size_t)i * XD_ * DI_;
        const float* dtw_i   = dtw   + (size_t)i * DI_ * DTR_;
        const float* dtb_i   = dtb   + (size_t)i * DI_;
        const float* alog_i  = alog  + (size_t)i * DI_ * DS_;
        const float* dskip_i = dskip + (size_t)i * DI_;
        const float* outw_i  = outw  + (size_t)i * D_ * DI_;

        // ---- attention ----
        gemm(px, D_, w_qkv_i, D_, b_qkv_i, pqkv, 3 * D_, R_, 3 * D_, D_, 0, 0);
        attn_scores_kernel<<<dim3(8, 8, B_ * NH_), 256>>>();
        softmax_rows_kernel<<<B_ * NH_ * L_, 256>>>();
        attn_pv_kernel<<<dim3(8, B_ * NH_), 256>>>();
        gemm(pctx, D_, w_o_i, D_, b_o_i, pa, D_, R_, D_, D_, 0, 0);

        // ---- mamba ----
        gemm(px, D_, inw_i, D_, nullptr, pxz, 2 * DI_, R_, 2 * DI_, D_, 0, 0);
        conv_silu_kernel<<<(R_ * DI_ + 255) / 256, 256>>>(cw_i, cb_i);
        gemm(pxc, DI_, xpw_i, DI_, nullptr, pxdbl, XD_, R_, XD_, DI_, 0, 0);
        gemm(pxdbl, XD_, dtw_i, DTR_, dtb_i, pdt, DI_, R_, DI_, DTR_, 2, 0);  // softplus
        scan_kernel<<<(B_ * DI_ * 32) / 256, 256>>>(alog_i, dskip_i);
        gemm(py, DI_, outw_i, DI_, nullptr, pa, D_, R_, D_, DI_, 0, 1);       // a += mamba

        // ---- FFN + LN ----
        gemm(pa, D_, w1_i, D_, b1_i, pff, FF_, R_, FF_, D_, 1, 0);            // relu
        gemm(pff, FF_, w2_i, FF_, b2_i, ph2, D_, R_, D_, FF_, 0, 0);
        layernorm_kernel<<<R_, 256>>>(ph2, n1g_i, n1b_i, px);
    }

    layernorm_kernel<<<R_, 256>>>(px, nfg, nfb, out);
}

// round 17
// speedup vs baseline: 1.5223x; 1.5223x over previous
#include <cuda_runtime.h>
#include <math.h>
#include <stdint.h>

// ---------------- problem constants ----------------
#define B_   4
#define L_   512
#define D_   512
#define NH_  8
#define FF_  2048
#define NL_  4
#define DS_  64
#define DC_  4
#define DI_  1024
#define DTR_ 32
#define HD_  64
#define R_   (B_ * L_)            // 2048 token rows
#define XD_  (DTR_ + 2 * DS_)     // 160

// ---------------- device scratch (no allocs allowed) ----------------
__device__ float g_x    [R_ * D_];          // running activation
__device__ float g_qkv  [R_ * 3 * D_];
__device__ float g_scores[B_ * NH_ * L_ * L_];
__device__ float g_ctx  [R_ * D_];
__device__ float g_a    [R_ * D_];          // attn out, then attn+mamba
__device__ float g_xz   [R_ * 2 * DI_];
__device__ float g_xc   [R_ * DI_];
__device__ float g_xdbl [R_ * XD_];
__device__ float g_dt   [R_ * DI_];
__device__ float g_y    [R_ * DI_];
__device__ float g_ff   [R_ * FF_];
__device__ float g_h2   [R_ * D_];

// ---------------- positional encoding ----------------
__global__ __launch_bounds__(256) void pos_encode_kernel(const float* __restrict__ src) {
    int idx = blockIdx.x * blockDim.x + threadIdx.x;
    if (idx >= R_ * D_) return;
    int d = idx % D_;
    int l = (idx / D_) % L_;
    int i2 = d & ~1;  // 2*(d/2)
    float div = expf(-(float)i2 * (9.210340371976184f / (float)D_));  // ln(10000)/D
    float ang = (float)l * div;
    float pe = (d & 1) ? cosf(ang) : sinf(ang);
    g_x[idx] = src[idx] + pe;
}

// ---------------- generic SGEMM: C = act(A(M,K) @ W(N,K)^T + bias [+ C]) ----------------
__global__ __launch_bounds__(256) void gemm_nt_kernel(
    const float* __restrict__ A, int lda,
    const float* __restrict__ W, int ldb,
    const float* __restrict__ bias,
    float* __restrict__ C, int ldc,
    int M, int N, int K, int act, int accum)
{
    __shared__ float As[16][68];
    __shared__ float Ws[16][68];
    const int tid = threadIdx.x;
    const int m0 = blockIdx.y * 64, n0 = blockIdx.x * 64;
    const int tr = tid >> 4, tc = tid & 15;

    float acc[4][4];
#pragma unroll
    for (int i = 0; i < 4; ++i)
#pragma unroll
        for (int j = 0; j < 4; ++j) acc[i][j] = 0.f;

    for (int k0 = 0; k0 < K; k0 += 16) {
#pragma unroll
        for (int i = 0; i < 4; ++i) {
            int idx = tid + i * 256;
            int r = idx >> 4, c = idx & 15;
            int m = m0 + r, k = k0 + c;
            float v = 0.f;
            if (m < M && k < K) v = A[(size_t)m * lda + k];
            As[c][r] = v;
        }
#pragma unroll
        for (int i = 0; i < 4; ++i) {
            int idx = tid + i * 256;
            int r = idx >> 4, c = idx & 15;
            int n = n0 + r, k = k0 + c;
            float v = 0.f;
            if (n < N && k < K) v = W[(size_t)n * ldb + k];
            Ws[c][r] = v;
        }
        __syncthreads();
#pragma unroll
        for (int kk = 0; kk < 16; ++kk) {
            float4 a4 = *reinterpret_cast<const float4*>(&As[kk][tr * 4]);
            float4 b4 = *reinterpret_cast<const float4*>(&Ws[kk][tc * 4]);
            float a[4] = {a4.x, a4.y, a4.z, a4.w};
            float b[4] = {b4.x, b4.y, b4.z, b4.w};
#pragma unroll
            for (int i = 0; i < 4; ++i)
#pragma unroll
                for (int j = 0; j < 4; ++j)
                    acc[i][j] = fmaf(a[i], b[j], acc[i][j]);
        }
        __syncthreads();
    }

#pragma unroll
    for (int i = 0; i < 4; ++i) {
        int m = m0 + tr * 4 + i;
        if (m >= M) continue;
#pragma unroll
        for (int j = 0; j < 4; ++j) {
            int n = n0 + tc * 4 + j;
            if (n >= N) continue;
            float v = acc[i][j];
            if (bias) v += bias[n];
            if (accum) v += C[(size_t)m * ldc + n];
            if (act == 1) v = fmaxf(v, 0.f);
            else if (act == 2) v = (v > 20.f) ? v : log1pf(expf(v));   // softplus
            C[(size_t)m * ldc + n] = v;
        }
    }
}

// ---------------- attention: scores = Q K^T / sqrt(HD) ----------------
// grid (8, 8, B*NH), 256 threads. qkv row layout: [q(512) | k(512) | v(512)]
__global__ __launch_bounds__(256) void attn_scores_kernel() {
    __shared__ float Qs[64][68];
    __shared__ float Ks[64][68];
    const int tid = threadIdx.x;
    const int z = blockIdx.z;
    const int b = z >> 3, h = z & 7;
    const int m0 = blockIdx.y * 64, n0 = blockIdx.x * 64;
    const float* Qb = g_qkv + (size_t)b * L_ * 1536 + h * 64;
    const float* Kb = Qb + 512;

#pragma unroll
    for (int i = 0; i < 16; ++i) {
        int idx = tid + i * 256;
        int r = idx >> 6, c = idx & 63;
        Qs[c][r] = Qb[(size_t)(m0 + r) * 1536 + c];
        Ks[c][r] = Kb[(size_t)(n0 + r) * 1536 + c];
    }
    __syncthreads();

    const int tr = tid >> 4, tc = tid & 15;
    float acc[4][4];
#pragma unroll
    for (int i = 0; i < 4; ++i)
#pragma unroll
        for (int j = 0; j < 4; ++j) acc[i][j] = 0.f;

#pragma unroll 8
    for (int kk = 0; kk < 64; ++kk) {
        float4 a4 = *reinterpret_cast<const float4*>(&Qs[kk][tr * 4]);
        float4 b4 = *reinterpret_cast<const float4*>(&Ks[kk][tc * 4]);
        float a[4] = {a4.x, a4.y, a4.z, a4.w};
        float b[4] = {b4.x, b4.y, b4.z, b4.w};
#pragma unroll
        for (int i = 0; i < 4; ++i)
#pragma unroll
            for (int j = 0; j < 4; ++j)
                acc[i][j] = fmaf(a[i], b[j], acc[i][j]);
    }

    float* Sb = g_scores + (size_t)z * L_ * L_;
#pragma unroll
    for (int i = 0; i < 4; ++i) {
        int m = m0 + tr * 4 + i;
#pragma unroll
        for (int j = 0; j < 4; ++j) {
            int n = n0 + tc * 4 + j;
            Sb[(size_t)m * L_ + n] = acc[i][j] * 0.125f;   // 1/sqrt(64)
        }
    }
}

// ---------------- row softmax over 512 cols ----------------
__global__ __launch_bounds__(256) void softmax_rows_kernel() {
    float* p = g_scores + (size_t)blockIdx.x * 512;
    const int tid = threadIdx.x;
    const int wid = tid >> 5, lane = tid & 31;
    __shared__ float rmax[8], rsum[8], bc[2];

    float s0 = p[tid], s1 = p[tid + 256];
    float m = fmaxf(s0, s1);
#pragma unroll
    for (int o = 16; o; o >>= 1) m = fmaxf(m, __shfl_xor_sync(0xffffffffu, m, o));
    if (lane == 0) rmax[wid] = m;
    __syncthreads();
    if (tid == 0) {
        float mm = rmax[0];
#pragma unroll
        for (int i = 1; i < 8; ++i) mm = fmaxf(mm, rmax[i]);
        bc[0] = mm;
    }
    __syncthreads();
    float M = bc[0];
    float e0 = __expf(s0 - M), e1 = __expf(s1 - M);
    float s = e0 + e1;
#pragma unroll
    for (int o = 16; o; o >>= 1) s += __shfl_xor_sync(0xffffffffu, s, o);
    if (lane == 0) rsum[wid] = s;
    __syncthreads();
    if (tid == 0) {
        float ss = 0.f;
#pragma unroll
        for (int i = 0; i < 8; ++i) ss += rsum[i];
        bc[1] = 1.f / ss;
    }
    __syncthreads();
    float inv = bc[1];
    p[tid] = e0 * inv;
    p[tid + 256] = e1 * inv;
}

// ---------------- attention: O = P @ V, heads merged into g_ctx ----------------
// grid (8 m-tiles, B*NH), 256 threads
__global__ __launch_bounds__(256) void attn_pv_kernel() {
    __shared__ float As[16][68];
    __shared__ float Bs[16][68];
    const int tid = threadIdx.x;
    const int z = blockIdx.y;
    const int b = z >> 3, h = z & 7;
    const int m0 = blockIdx.x * 64;
    const float* P = g_scores + (size_t)z * L_ * L_;
    const float* V = g_qkv + (size_t)b * L_ * 1536 + 1024 + h * 64;

    const int tr = tid >> 4, tc = tid & 15;
    float acc[4][4];
#pragma unroll
    for (int i = 0; i < 4; ++i)
#pragma unroll
        for (int j = 0; j < 4; ++j) acc[i][j] = 0.f;

    for (int k0 = 0; k0 < L_; k0 += 16) {
#pragma unroll
        for (int i = 0; i < 4; ++i) {
            int idx = tid + i * 256;
            int r = idx >> 4, c = idx & 15;
            As[c][r] = P[(size_t)(m0 + r) * 512 + k0 + c];
        }
#pragma unroll
        for (int i = 0; i < 4; ++i) {
            int idx = tid + i * 256;
            int kk = idx >> 6, n = idx & 63;
            Bs[kk][n] = V[(size_t)(k0 + kk) * 1536 + n];
        }
        __syncthreads();
#pragma unroll
        for (int kk = 0; kk < 16; ++kk) {
            float4 a4 = *reinterpret_cast<const float4*>(&As[kk][tr * 4]);
            float4 b4 = *reinterpret_cast<const float4*>(&Bs[kk][tc * 4]);
            float a[4] = {a4.x, a4.y, a4.z, a4.w};
            float b[4] = {b4.x, b4.y, b4.z, b4.w};
#pragma unroll
            for (int i = 0; i < 4; ++i)
#pragma unroll
                for (int j = 0; j < 4; ++j)
                    acc[i][j] = fmaf(a[i], b[j], acc[i][j]);
        }
        __syncthreads();
    }

#pragma unroll
    for (int i = 0; i < 4; ++i) {
        int m = m0 + tr * 4 + i;
#pragma unroll
        for (int j = 0; j < 4; ++j) {
            int n = tc * 4 + j;
            g_ctx[(size_t)(b * L_ + m) * D_ + h * 64 + n] = acc[i][j];
        }
    }
}

// ---------------- depthwise causal conv1d (DC=4) + SiLU ----------------
__global__ __launch_bounds__(256) void conv_silu_kernel(
    const float* __restrict__ conv_w, const float* __restrict__ conv_b)
{
    int idx = blockIdx.x * blockDim.x + threadIdx.x;
    if (idx >= R_ * DI_) return;
    int d = idx % DI_;
    int t = (idx / DI_) % L_;
    int b = idx / (DI_ * L_);
    const float* w = conv_w + d * 4;
    const float* xin = g_xz + (size_t)b * L_ * (2 * DI_) + d;
    float acc = conv_b[d];
#pragma unroll
    for (int k = 0; k < 4; ++k) {
        int tt = t - 3 + k;
        if (tt >= 0) acc = fmaf(w[k], xin[(size_t)tt * (2 * DI_)], acc);
    }
    float sig = 1.f / (1.f + __expf(-acc));
    g_xc[idx] = acc * sig;
}

// ---------------- mamba selective scan: one warp per (b,d), 2 states/lane ----------------
__global__ __launch_bounds__(256) void scan_kernel(
    const float* __restrict__ A_log, const float* __restrict__ D_skip)
{
    int w = (blockIdx.x * blockDim.x + threadIdx.x) >> 5;
    int lane = threadIdx.x & 31;
    int b = w >> 10;          // / DI_
    int d = w & (DI_ - 1);
    int n0 = lane * 2;

    float a0 = -expf(A_log[d * DS_ + n0]);
    float a1 = -expf(A_log[d * DS_ + n0 + 1]);
    float dsk = D_skip[d];
    float h0 = 0.f, h1 = 0.f;

    const float* dtp = g_dt   + (size_t)b * L_ * DI_ + d;
    const float* up  = g_xc   + (size_t)b * L_ * DI_ + d;
    const float* xd  = g_xdbl + (size_t)b * L_ * XD_;
    const float* zp  = g_xz   + (size_t)b * L_ * (2 * DI_) + DI_ + d;
    float*       yp  = g_y    + (size_t)b * L_ * DI_ + d;

    for (int t = 0; t < L_; ++t) {
        float dt = dtp[(size_t)t * DI_];
        float u  = up [(size_t)t * DI_];
        const float* row = xd + (size_t)t * XD_;
        float2 Bn = *reinterpret_cast<const float2*>(row + DTR_ + n0);
        float2 Cn = *reinterpret_cast<const float2*>(row + DTR_ + DS_ + n0);
        float e0 = __expf(dt * a0), e1 = __expf(dt * a1);
        float du = dt * u;
        h0 = fmaf(e0, h0, du * Bn.x);
        h1 = fmaf(e1, h1, du * Bn.y);
        float y = fmaf(h0, Cn.x, h1 * Cn.y);
#pragma unroll
        for (int o = 16; o; o >>= 1) y += __shfl_xor_sync(0xffffffffu, y, o);
        if (lane == 0) {
            float z = zp[(size_t)t * (2 * DI_)];
            float sil = z / (1.f + __expf(-z));
            yp[(size_t)t * DI_] = (y + u * dsk) * sil;
        }
    }
}

// ---------------- layernorm over D=512 ----------------
__global__ __launch_bounds__(256) void layernorm_kernel(
    const float* __restrict__ in, const float* __restrict__ g,
    const float* __restrict__ bta, float* __restrict__ out)
{
    const float* p = in + (size_t)blockIdx.x * D_;
    float* q = out + (size_t)blockIdx.x * D_;
    const int tid = threadIdx.x;
    const int wid = tid >> 5, lane = tid & 31;
    __shared__ float rs[8], rq[8], bc[2];

    float x0 = p[tid], x1 = p[tid + 256];
    float s = x0 + x1, sq = x0 * x0 + x1 * x1;
#pragma unroll
    for (int o = 16; o; o >>= 1) {
        s  += __shfl_xor_sync(0xffffffffu, s, o);
        sq += __shfl_xor_sync(0xffffffffu, sq, o);
    }
    if (lane == 0) { rs[wid] = s; rq[wid] = sq; }
    __syncthreads();
    if (tid == 0) {
        float S = 0.f, SQ = 0.f;
#pragma unroll
        for (int i = 0; i < 8; ++i) { S += rs[i]; SQ += rq[i]; }
        float mean = S * (1.f / D_);
        float var  = SQ * (1.f / D_) - mean * mean;
        bc[0] = mean;
        bc[1] = rsqrtf(var + 1e-5f);
    }
    __syncthreads();
    float mean = bc[0], inv = bc[1];
    q[tid]        = (x0 - mean) * inv * g[tid]        + bta[tid];
    q[tid + 256]  = (x1 - mean) * inv * g[tid + 256]  + bta[tid + 256];
}

// ---------------- host side ----------------
static void gemm(const float* A, int lda, const float* W, int ldb, const float* bias,
                 float* C, int ldc, int M, int N, int K, int act, int accum)
{
    dim3 grid((N + 63) / 64, (M + 63) / 64);
    gemm_nt_kernel<<<grid, 256>>>(A, lda, W, ldb, bias, C, ldc, M, N, K, act, accum);
}

extern "C" void kernel_launch(void* const* d_in, const int* in_sizes, int n_in,
                              void* d_out, int out_size)
{
    (void)in_sizes; (void)n_in; (void)out_size;
    const float* src    = (const float*)d_in[0];
    const float* w_qkv  = (const float*)d_in[1];
    const float* b_qkv  = (const float*)d_in[2];
    const float* w_o    = (const float*)d_in[3];
    const float* b_o    = (const float*)d_in[4];
    const float* w1     = (const float*)d_in[5];
    const float* b1     = (const float*)d_in[6];
    const float* w2     = (const float*)d_in[7];
    const float* b2     = (const float*)d_in[8];
    const float* n1g    = (const float*)d_in[9];
    const float* n1b    = (const float*)d_in[10];
    const float* inw    = (const float*)d_in[11];
    const float* cw     = (const float*)d_in[12];
    const float* cb     = (const float*)d_in[13];
    const float* xpw    = (const float*)d_in[14];
    const float* dtw    = (const float*)d_in[15];
    const float* dtb    = (const float*)d_in[16];
    const float* alog   = (const float*)d_in[17];
    const float* dskip  = (const float*)d_in[18];
    const float* outw   = (const float*)d_in[19];
    const float* nfg    = (const float*)d_in[20];
    const float* nfb    = (const float*)d_in[21];
    float* out = (float*)d_out;

    float *px, *pqkv, *pctx, *pa, *pxz, *pxc, *pxdbl, *pdt, *py, *pff, *ph2;
    cudaGetSymbolAddress((void**)&px,    g_x);
    cudaGetSymbolAddress((void**)&pqkv,  g_qkv);
    cudaGetSymbolAddress((void**)&pctx,  g_ctx);
    cudaGetSymbolAddress((void**)&pa,    g_a);
    cudaGetSymbolAddress((void**)&pxz,   g_xz);
    cudaGetSymbolAddress((void**)&pxc,   g_xc);
    cudaGetSymbolAddress((void**)&pxdbl, g_xdbl);
    cudaGetSymbolAddress((void**)&pdt,   g_dt);
    cudaGetSymbolAddress((void**)&py,    g_y);
    cudaGetSymbolAddress((void**)&pff,   g_ff);
    cudaGetSymbolAddress((void**)&ph2,   g_h2);

    pos_encode_kernel<<<(R_ * D_ + 255) / 256, 256>>>(src);

    for (int i = 0; i < NL_; ++i) {
        const float* w_qkv_i = w_qkv + (size_t)i * 3 * D_ * D_;
        const float* b_qkv_i = b_qkv + (size_t)i * 3 * D_;
        const float* w_o_i   = w_o   + (size_t)i * D_ * D_;
        const float* b_o_i   = b_o   + (size_t)i * D_;
        const float* w1_i    = w1    + (size_t)i * FF_ * D_;
        const float* b1_i    = b1    + (size_t)i * FF_;
        const float* w2_i    = w2    + (size_t)i * D_ * FF_;
        const float* b2_i    = b2    + (size_t)i * D_;
        const float* n1g_i   = n1g   + (size_t)i * D_;
        const float* n1b_i   = n1b   + (size_t)i * D_;
        const float* inw_i   = inw   + (size_t)i * 2 * DI_ * D_;
        const float* cw_i    = cw    + (size_t)i * DI_ * DC_;
        const float* cb_i    = cb    + (size_t)i * DI_;
        const float* xpw_i   = xpw   + (size_t)i * XD_ * DI_;
        const float* dtw_i   = dtw   + (size_t)i * DI_ * DTR_;
        const float* dtb_i   = dtb   + (size_t)i * DI_;
        const float* alog_i  = alog  + (size_t)i * DI_ * DS_;
        const float* dskip_i = dskip + (size_t)i * DI_;
        const float* outw_i  = outw  + (size_t)i * D_ * DI_;

        // ---- attention ----
        gemm(px, D_, w_qkv_i, D_, b_qkv_i, pqkv, 3 * D_, R_, 3 * D_, D_, 0, 0);
        attn_scores_kernel<<<dim3(8, 8, B_ * NH_), 256>>>();
        softmax_rows_kernel<<<B_ * NH_ * L_, 256>>>();
        attn_pv_kernel<<<dim3(8, B_ * NH_), 256>>>();
        gemm(pctx, D_, w_o_i, D_, b_o_i, pa, D_, R_, D_, D_, 0, 0);

        // ---- mamba ----
        gemm(px, D_, inw_i, D_, nullptr, pxz, 2 * DI_, R_, 2 * DI_, D_, 0, 0);
        conv_silu_kernel<<<(R_ * DI_ + 255) / 256, 256>>>(cw_i, cb_i);
        gemm(pxc, DI_, xpw_i, DI_, nullptr, pxdbl, XD_, R_, XD_, DI_, 0, 0);
        gemm(pxdbl, XD_, dtw_i, DTR_, dtb_i, pdt, DI_, R_, DI_, DTR_, 2, 0);  // softplus
        scan_kernel<<<(B_ * DI_ * 32) / 256, 256>>>(alog_i, dskip_i);
        gemm(py, DI_, outw_i, DI_, nullptr, pa, D_, R_, D_, DI_, 0, 1);       // a += mamba

        // ---- FFN + LN ----
        gemm(pa, D_, w1_i, D_, b1_i, pff, FF_, R_, FF_, D_, 1, 0);            // relu
        gemm(pff, FF_, w2_i, FF_, b2_i, ph2, D_, R_, D_, FF_, 0, 0);
        layernorm_kernel<<<R_, 256>>>(ph2, n1g_i, n1b_i, px);
    }

    layernorm_kernel<<<R_, 256>>>(px, nfg, nfb, out);
}